// round 4
// baseline (speedup 1.0000x reference)
#include <cuda_runtime.h>
#include <math.h>

// Problem constants
// B=2, S=2048, DM=1024, H=16, HKV=4, HD=64, REP=4, THETA=10000

// ---------------- device scratch (no allocation allowed) ----------------
__device__ float g_Q[2 * 16 * 2048 * 64];   // [B,H,S,HD]
__device__ float g_K[2 * 4 * 2048 * 64];    // [B,HKV,S,HD]
__device__ float g_V[2 * 4 * 2048 * 64];    // [B,HKV,S,HD]
__device__ float g_att[2 * 2048 * 1024];    // [B,S,H*HD]

// =========================================================================
// Tiled fp32 GEMM: Y = X @ W.  X:[4096,1024], W:[1024,N].
// NH > 0 : scatter output column n -> head h=n/64, Y layout [B,NH,S,64]
// NH == 0: plain row-major Y [4096,1024]
// Block: 256 threads (16x16), tile 64x64, k-step 16, 4x4 micro-tile.
// =========================================================================
template <int NH>
__global__ __launch_bounds__(256)
void gemm_kernel(const float* __restrict__ X, const float* __restrict__ W,
                 float* __restrict__ Y, int N) {
    __shared__ float As[16][68];  // A transposed: [k][m]
    __shared__ float Bs[16][68];  // [k][n]

    const int tid = threadIdx.x;
    const int tx = tid & 15, ty = tid >> 4;
    const int m0 = blockIdx.y * 64;
    const int n0 = blockIdx.x * 64;

    const int arow = tid >> 2,  akc = (tid & 3) * 4;    // A loader: row 0..63, kcol
    const int brow = tid >> 4,  bnc = (tid & 15) * 4;   // B loader: krow 0..15, ncol

    float acc[4][4] = {};

    for (int k0 = 0; k0 < 1024; k0 += 16) {
        float4 a = *(const float4*)&X[(size_t)(m0 + arow) * 1024 + k0 + akc];
        As[akc + 0][arow] = a.x;
        As[akc + 1][arow] = a.y;
        As[akc + 2][arow] = a.z;
        As[akc + 3][arow] = a.w;
        *(float4*)&Bs[brow][bnc] =
            *(const float4*)&W[(size_t)(k0 + brow) * N + n0 + bnc];
        __syncthreads();

#pragma unroll
        for (int kk = 0; kk < 16; ++kk) {
            float4 av = *(float4*)&As[kk][4 * ty];
            float4 bv = *(float4*)&Bs[kk][4 * tx];
            acc[0][0] += av.x * bv.x; acc[0][1] += av.x * bv.y;
            acc[0][2] += av.x * bv.z; acc[0][3] += av.x * bv.w;
            acc[1][0] += av.y * bv.x; acc[1][1] += av.y * bv.y;
            acc[1][2] += av.y * bv.z; acc[1][3] += av.y * bv.w;
            acc[2][0] += av.z * bv.x; acc[2][1] += av.z * bv.y;
            acc[2][2] += av.z * bv.z; acc[2][3] += av.z * bv.w;
            acc[3][0] += av.w * bv.x; acc[3][1] += av.w * bv.y;
            acc[3][2] += av.w * bv.z; acc[3][3] += av.w * bv.w;
        }
        __syncthreads();
    }

#pragma unroll
    for (int i = 0; i < 4; ++i) {
        const int r = m0 + 4 * ty + i;
        float4 v = make_float4(acc[i][0], acc[i][1], acc[i][2], acc[i][3]);
        if constexpr (NH > 0) {
            // n0 is a multiple of 64 and tile width = 64 -> head index == blockIdx.x
            const int b = r >> 11;        // r / 2048
            const int sidx = r & 2047;    // r % 2048
            *(float4*)&Y[(((size_t)(b * NH + blockIdx.x)) * 2048 + sidx) * 64 +
                         4 * tx] = v;
        } else {
            *(float4*)&Y[(size_t)r * 1024 + n0 + 4 * tx] = v;
        }
    }
}

// =========================================================================
// Continuous 2D RoPE over T:[B*NH, S, 64].  One thread per (bh, s, pair p).
// x-half (dims 0..31) rotated with coords[:,0]; y-half (32..63) with coords[:,1].
// inv_freq[p] = 10000^(-p/16),  p = 0..15.
// =========================================================================
__global__ __launch_bounds__(256)
void rope_kernel(float* __restrict__ T, const float* __restrict__ pos) {
    const int idx = blockIdx.x * blockDim.x + threadIdx.x;
    const int p  = idx & 15;
    const int s  = (idx >> 4) & 2047;
    const int bh = idx >> 15;

    // 10000^(-p/16) = exp2(-p * log2(10000)/16)
    const float inv = exp2f((float)p * (-13.287712379549449f / 16.0f));
    const float cx = pos[2 * s];
    const float cy = pos[2 * s + 1];
    float sinx, cosx, siny, cosy;
    sincosf(cx * inv, &sinx, &cosx);
    sincosf(cy * inv, &siny, &cosy);

    float* base = T + ((size_t)bh * 2048 + s) * 64;

    float a0 = base[2 * p], a1 = base[2 * p + 1];
    base[2 * p]     = a0 * cosx - a1 * sinx;
    base[2 * p + 1] = a1 * cosx + a0 * sinx;

    float b0 = base[32 + 2 * p], b1 = base[33 + 2 * p];
    base[32 + 2 * p] = b0 * cosy - b1 * siny;
    base[33 + 2 * p] = b1 * cosy + b0 * siny;
}

// =========================================================================
// Flash attention (non-causal, full softmax), fp32.
// Grid: (S/64, B*H). Block: 256 threads (16x16).
// Per block: 64 queries x HD=64; loop over 32 KV tiles of 64 keys.
// Online softmax in registers; P staged via smem for the PV product.
// Writes result into g_att laid out [B, S, H*64] (ready for the Wo GEMM).
// =========================================================================
#define SMEM_ATTN ((3 * 64 * 64 + 64 * 68) * 4)  // Qs,Vs,Ps (64x64) + KsT (64x68)

__global__ __launch_bounds__(256)
void attn_kernel(const float* __restrict__ Q, const float* __restrict__ K,
                 const float* __restrict__ V, float* __restrict__ Oa) {
    extern __shared__ float sm[];
    float* Qs  = sm;                 // [64 q][64 d]
    float* Vs  = Qs + 64 * 64;       // [64 k][64 d]
    float* Ps  = Vs + 64 * 64;       // [64 q][64 k]
    float* KsT = Ps + 64 * 64;       // [64 d][68]  (d-major, padded)

    const int tid = threadIdx.x;
    const int tx = tid & 15, ty = tid >> 4;
    const int qt = blockIdx.x * 64;
    const int bh = blockIdx.y;            // b*16 + h
    const int b = bh >> 4, h = bh & 15;
    const int hkv = h >> 2;               // GQA: 4 query heads per kv head

    const float* Qg = Q + (((size_t)bh) * 2048 + qt) * 64;
    const float* Kg = K + ((size_t)(b * 4 + hkv)) * 2048 * 64;
    const float* Vg = V + ((size_t)(b * 4 + hkv)) * 2048 * 64;

    const int lr = tid >> 4;              // 0..15
    const int lc = (tid & 15) * 4;        // 0..60

    // Load Q tile
#pragma unroll
    for (int r = 0; r < 4; ++r) {
        const int row = r * 16 + lr;
        *(float4*)&Qs[row * 64 + lc] = *(const float4*)&Qg[row * 64 + lc];
    }

    float m[4], l[4], o[4][4];
#pragma unroll
    for (int i = 0; i < 4; ++i) {
        m[i] = -1e30f;
        l[i] = 0.0f;
#pragma unroll
        for (int j = 0; j < 4; ++j) o[i][j] = 0.0f;
    }
    __syncthreads();

    for (int kt = 0; kt < 2048; kt += 64) {
        // Load K tile transposed (d-major) and V tile
#pragma unroll
        for (int r = 0; r < 4; ++r) {
            const int row = r * 16 + lr;
            float4 kv = *(const float4*)&Kg[(size_t)(kt + row) * 64 + lc];
            KsT[(lc + 0) * 68 + row] = kv.x;
            KsT[(lc + 1) * 68 + row] = kv.y;
            KsT[(lc + 2) * 68 + row] = kv.z;
            KsT[(lc + 3) * 68 + row] = kv.w;
            *(float4*)&Vs[row * 64 + lc] =
                *(const float4*)&Vg[(size_t)(kt + row) * 64 + lc];
        }
        __syncthreads();

        // S = Q @ K^T  (4x4 micro-tile per thread)
        float s[4][4];
#pragma unroll
        for (int i = 0; i < 4; ++i)
#pragma unroll
            for (int j = 0; j < 4; ++j) s[i][j] = 0.0f;

#pragma unroll 16
        for (int d = 0; d < 64; ++d) {
            float4 kk = *(float4*)&KsT[d * 68 + 4 * tx];
            float q0 = Qs[(4 * ty + 0) * 64 + d];
            float q1 = Qs[(4 * ty + 1) * 64 + d];
            float q2 = Qs[(4 * ty + 2) * 64 + d];
            float q3 = Qs[(4 * ty + 3) * 64 + d];
            s[0][0] += q0 * kk.x; s[0][1] += q0 * kk.y;
            s[0][2] += q0 * kk.z; s[0][3] += q0 * kk.w;
            s[1][0] += q1 * kk.x; s[1][1] += q1 * kk.y;
            s[1][2] += q1 * kk.z; s[1][3] += q1 * kk.w;
            s[2][0] += q2 * kk.x; s[2][1] += q2 * kk.y;
            s[2][2] += q2 * kk.z; s[2][3] += q2 * kk.w;
            s[3][0] += q3 * kk.x; s[3][1] += q3 * kk.y;
            s[3][2] += q3 * kk.z; s[3][3] += q3 * kk.w;
        }

        // Online softmax update (rows owned by ty; reduce across 16 tx lanes)
        const float scale = 0.125f;  // 1/sqrt(64)
#pragma unroll
        for (int i = 0; i < 4; ++i) {
#pragma unroll
            for (int j = 0; j < 4; ++j) s[i][j] *= scale;
            float mx = fmaxf(fmaxf(s[i][0], s[i][1]), fmaxf(s[i][2], s[i][3]));
            mx = fmaxf(mx, __shfl_xor_sync(0xffffffffu, mx, 1));
            mx = fmaxf(mx, __shfl_xor_sync(0xffffffffu, mx, 2));
            mx = fmaxf(mx, __shfl_xor_sync(0xffffffffu, mx, 4));
            mx = fmaxf(mx, __shfl_xor_sync(0xffffffffu, mx, 8));
            const float mn = fmaxf(m[i], mx);
            const float alpha = __expf(m[i] - mn);
            m[i] = mn;
            float rs = 0.0f;
#pragma unroll
            for (int j = 0; j < 4; ++j) {
                s[i][j] = __expf(s[i][j] - mn);
                rs += s[i][j];
            }
            rs += __shfl_xor_sync(0xffffffffu, rs, 1);
            rs += __shfl_xor_sync(0xffffffffu, rs, 2);
            rs += __shfl_xor_sync(0xffffffffu, rs, 4);
            rs += __shfl_xor_sync(0xffffffffu, rs, 8);
            l[i] = l[i] * alpha + rs;
#pragma unroll
            for (int j = 0; j < 4; ++j) o[i][j] *= alpha;
            *(float4*)&Ps[(4 * ty + i) * 64 + 4 * tx] =
                make_float4(s[i][0], s[i][1], s[i][2], s[i][3]);
        }
        __syncthreads();

        // O += P @ V
#pragma unroll 16
        for (int k = 0; k < 64; ++k) {
            float4 vv = *(float4*)&Vs[k * 64 + 4 * tx];
            float p0 = Ps[(4 * ty + 0) * 64 + k];
            float p1 = Ps[(4 * ty + 1) * 64 + k];
            float p2 = Ps[(4 * ty + 2) * 64 + k];
            float p3 = Ps[(4 * ty + 3) * 64 + k];
            o[0][0] += p0 * vv.x; o[0][1] += p0 * vv.y;
            o[0][2] += p0 * vv.z; o[0][3] += p0 * vv.w;
            o[1][0] += p1 * vv.x; o[1][1] += p1 * vv.y;
            o[1][2] += p1 * vv.z; o[1][3] += p1 * vv.w;
            o[2][0] += p2 * vv.x; o[2][1] += p2 * vv.y;
            o[2][2] += p2 * vv.z; o[2][3] += p2 * vv.w;
            o[3][0] += p3 * vv.x; o[3][1] += p3 * vv.y;
            o[3][2] += p3 * vv.z; o[3][3] += p3 * vv.w;
        }
        __syncthreads();
    }

    // Epilogue: normalize and write to [B, S, H*64]
#pragma unroll
    for (int i = 0; i < 4; ++i) {
        const float invl = 1.0f / l[i];
        const int srow = qt + 4 * ty + i;
        float4 r = make_float4(o[i][0] * invl, o[i][1] * invl,
                               o[i][2] * invl, o[i][3] * invl);
        *(float4*)&Oa[((size_t)(b * 2048 + srow)) * 1024 + h * 64 + 4 * tx] = r;
    }
}

// =========================================================================
// Launch
// =========================================================================
extern "C" void kernel_launch(void* const* d_in, const int* in_sizes, int n_in,
                              void* d_out, int out_size) {
    (void)in_sizes; (void)n_in; (void)out_size;
    const float* x   = (const float*)d_in[0];
    const float* pos = (const float*)d_in[1];
    const float* Wq  = (const float*)d_in[2];
    const float* Wk  = (const float*)d_in[3];
    const float* Wv  = (const float*)d_in[4];
    const float* Wo  = (const float*)d_in[5];
    float* out = (float*)d_out;

    float *qp, *kp, *vp, *ap;
    cudaGetSymbolAddress((void**)&qp, g_Q);
    cudaGetSymbolAddress((void**)&kp, g_K);
    cudaGetSymbolAddress((void**)&vp, g_V);
    cudaGetSymbolAddress((void**)&ap, g_att);

    // QKV projections (scattered into per-head layouts)
    gemm_kernel<16><<<dim3(16, 64), 256>>>(x, Wq, qp, 1024);
    gemm_kernel<4><<<dim3(4, 64), 256>>>(x, Wk, kp, 256);
    gemm_kernel<4><<<dim3(4, 64), 256>>>(x, Wv, vp, 256);

    // RoPE on Q (B*H*S*16 threads) and K (B*HKV*S*16 threads)
    rope_kernel<<<4096, 256>>>(qp, pos);
    rope_kernel<<<1024, 256>>>(kp, pos);

    // Flash attention
    cudaFuncSetAttribute(attn_kernel, cudaFuncAttributeMaxDynamicSharedMemorySize,
                         SMEM_ATTN);
    attn_kernel<<<dim3(32, 32), 256, SMEM_ATTN>>>(qp, kp, vp, ap);

    // Output projection
    gemm_kernel<0><<<dim3(16, 64), 256>>>(ap, Wo, out, 1024);
}